// round 5
// baseline (speedup 1.0000x reference)
#include <cuda_runtime.h>
#include <cuda_fp16.h>
#include <cstddef>

#define BB 256      // batch
#define TT 2048     // time steps
#define HH 64       // hidden
#define GG 256      // 4*H gates

typedef unsigned long long u64;

// ---------------- packed f32x2 helpers (sm_100+) ----------------
__device__ __forceinline__ u64 fma2(u64 a, u64 b, u64 c) {
    u64 d;
    asm("fma.rn.f32x2 %0, %1, %2, %3;" : "=l"(d) : "l"(a), "l"(b), "l"(c));
    return d;
}
__device__ __forceinline__ u64 add2(u64 a, u64 b) {
    u64 d;
    asm("add.rn.f32x2 %0, %1, %2;" : "=l"(d) : "l"(a), "l"(b));
    return d;
}
__device__ __forceinline__ float hsum2(u64 a) {
    float lo = __uint_as_float((unsigned)(a & 0xffffffffull));
    float hi = __uint_as_float((unsigned)(a >> 32));
    return lo + hi;
}

// MUFU-based fast activations
__device__ __forceinline__ float tanh_ap(float x) {
    float y;
    asm("tanh.approx.f32 %0, %1;" : "=f"(y) : "f"(x));
    return y;
}
__device__ __forceinline__ float sig_ap(float x) {
    return fmaf(0.5f, tanh_ap(0.5f * x), 0.5f);
}

// ---------------- device scratch (no cudaMalloc allowed) ----------------
__device__ __half g_y0[(size_t)BB * TT * HH];    // 64 MB, layer0 hidden outputs (fp16)
__device__ __half g_xp1[(size_t)BB * TT * GG];   // 256 MB, layer1 input projections (fp16)
__device__ float  g_y1[(size_t)BB * TT * HH];    // 128 MB, layer1 hidden outputs

// ---------------- LSTM recurrence kernel: 2 batch rows per CTA ----------------
// Grid = 128 CTAs (one per SM), 128 threads each. CTA handles batch rows
// bA=2*bid, bB=2*bid+1 with SHARED weights. Thread t owns gate rows t and
// t+128 for BOTH batch rows: 64 fma2/step fed by 32 LDS.128; the two batch
// rows' dependency chains interleave to fill issue slots.
// Gate rows: [0:64)=i [64:128)=f [128:192)=g [192:256)=o.
// Thread u<64 locally has (i,g) of unit u for A and B; thread u+64 has (f,o).
// Staging: low threads publish B's (i,g); high threads publish A's (f,o).
// Phase 2: low threads update batch A unit u; high threads update batch B.
template <int LAYER>
__global__ __launch_bounds__(128, 1) void lstm_recur_kernel(
    const float* __restrict__ x,     // LAYER==0: input [B,T]
    const float* __restrict__ Wih,   // LAYER==0: [256,1]
    const float* __restrict__ Whh,   // [256,64] row-major
    const float* __restrict__ bih,
    const float* __restrict__ bhh,
    const float* __restrict__ h0,    // [B,64] (already offset per layer)
    const float* __restrict__ c0)    // [B,64]
{
    __shared__ __align__(16) float  hA_sh[HH];
    __shared__ __align__(16) float  hB_sh[HH];
    __shared__ __align__(8)  float2 foA_sh[HH];   // (f,o) of batch A, by high threads
    __shared__ __align__(8)  float2 igB_sh[HH];   // (i,g) of batch B, by low threads

    const int tid  = threadIdx.x;
    const int bA   = 2 * blockIdx.x;
    const int bB   = bA + 1;
    const int g0   = tid;          // rows 0-63: i, 64-127: f   (sigmoid)
    const int g1   = tid + 128;    // rows 128-191: g (tanh), 192-255: o (sigmoid)
    const int unit = tid & 63;
    const bool low = (tid < 64);

    // ---- load both Whh rows into registers (packed pairs) ----
    u64 w0[32], w1[32];
    {
        const ulonglong2* r0 = (const ulonglong2*)(Whh + (size_t)g0 * HH);
        const ulonglong2* r1 = (const ulonglong2*)(Whh + (size_t)g1 * HH);
#pragma unroll
        for (int i = 0; i < 16; i++) {
            ulonglong2 v0 = r0[i];
            ulonglong2 v1 = r1[i];
            w0[2 * i] = v0.x; w0[2 * i + 1] = v0.y;
            w1[2 * i] = v1.x; w1[2 * i + 1] = v1.y;
        }
    }
    const float bias0 = bih[g0] + bhh[g0];
    const float bias1 = bih[g1] + bhh[g1];
    const float wx0 = (LAYER == 0) ? Wih[g0] : 0.0f;
    const float wx1 = (LAYER == 0) ? Wih[g1] : 0.0f;

    // cell state: low threads carry batch A's unit, high threads batch B's
    float c;
    if (low) {
        c = c0[(size_t)bA * HH + unit];
        hA_sh[unit] = h0[(size_t)bA * HH + unit];
    } else {
        c = c0[(size_t)bB * HH + unit];
        hB_sh[unit] = h0[(size_t)bB * HH + unit];
    }
    __syncthreads();

    const size_t xbA = (size_t)bA * TT;
    const size_t xbB = (size_t)bB * TT;
    const size_t pA  = (size_t)bA * TT * GG;   // xp1 base batch A
    const size_t pB  = (size_t)bB * TT * GG;
    const size_t yA  = (size_t)bA * TT * HH;
    const size_t yB  = (size_t)bB * TT * HH;

    // ---- input prefetch, 4 steps deep ----
    float vA[4], vB[4];          // LAYER 0: raw x per batch
    float xA0[4], xA1[4], xB0[4], xB1[4];  // LAYER 1: xp per (batch,row)
#pragma unroll
    for (int k = 0; k < 4; k++) {
        if (LAYER == 0) {
            vA[k] = __ldg(x + xbA + k);
            vB[k] = __ldg(x + xbB + k);
        } else {
            xA0[k] = __half2float(__ldg(g_xp1 + pA + (size_t)k * GG + g0));
            xA1[k] = __half2float(__ldg(g_xp1 + pA + (size_t)k * GG + g1));
            xB0[k] = __half2float(__ldg(g_xp1 + pB + (size_t)k * GG + g0));
            xB1[k] = __half2float(__ldg(g_xp1 + pB + (size_t)k * GG + g1));
        }
    }

#pragma unroll 2
    for (int t = 0; t < TT; t++) {
        // ---- phase 1: 4 gate pre-activations (2 rows x 2 batches) ----
        u64 aA0 = 0ull, aA1 = 0ull, aA2 = 0ull, aA3 = 0ull;   // row g0, batch A
        u64 dA0 = 0ull, dA1 = 0ull, dA2 = 0ull, dA3 = 0ull;   // row g1, batch A
        u64 aB0 = 0ull, aB1 = 0ull, aB2 = 0ull, aB3 = 0ull;   // row g0, batch B
        u64 dB0 = 0ull, dB1 = 0ull, dB2 = 0ull, dB3 = 0ull;   // row g1, batch B
        const ulonglong2* hA = (const ulonglong2*)hA_sh;
        const ulonglong2* hB = (const ulonglong2*)hB_sh;
#pragma unroll
        for (int i = 0; i < 8; i++) {
            ulonglong2 ha1 = hA[2 * i];
            ulonglong2 hb1 = hB[2 * i];
            ulonglong2 ha2 = hA[2 * i + 1];
            ulonglong2 hb2 = hB[2 * i + 1];
            aA0 = fma2(w0[4 * i + 0], ha1.x, aA0);
            aB0 = fma2(w0[4 * i + 0], hb1.x, aB0);
            dA0 = fma2(w1[4 * i + 0], ha1.x, dA0);
            dB0 = fma2(w1[4 * i + 0], hb1.x, dB0);
            aA1 = fma2(w0[4 * i + 1], ha1.y, aA1);
            aB1 = fma2(w0[4 * i + 1], hb1.y, aB1);
            dA1 = fma2(w1[4 * i + 1], ha1.y, dA1);
            dB1 = fma2(w1[4 * i + 1], hb1.y, dB1);
            aA2 = fma2(w0[4 * i + 2], ha2.x, aA2);
            aB2 = fma2(w0[4 * i + 2], hb2.x, aB2);
            dA2 = fma2(w1[4 * i + 2], ha2.x, dA2);
            dB2 = fma2(w1[4 * i + 2], hb2.x, dB2);
            aA3 = fma2(w0[4 * i + 3], ha2.y, aA3);
            aB3 = fma2(w0[4 * i + 3], hb2.y, aB3);
            dA3 = fma2(w1[4 * i + 3], ha2.y, dA3);
            dB3 = fma2(w1[4 * i + 3], hb2.y, dB3);
        }
        aA0 = add2(aA0, aA1); aA2 = add2(aA2, aA3); aA0 = add2(aA0, aA2);
        dA0 = add2(dA0, dA1); dA2 = add2(dA2, dA3); dA0 = add2(dA0, dA2);
        aB0 = add2(aB0, aB1); aB2 = add2(aB2, aB3); aB0 = add2(aB0, aB2);
        dB0 = add2(dB0, dB1); dB2 = add2(dB2, dB3); dB0 = add2(dB0, dB2);

        float preA0, preA1, preB0, preB1;
        if (LAYER == 0) {
            preA0 = fmaf(vA[0], wx0, bias0) + hsum2(aA0);
            preA1 = fmaf(vA[0], wx1, bias1) + hsum2(dA0);
            preB0 = fmaf(vB[0], wx0, bias0) + hsum2(aB0);
            preB1 = fmaf(vB[0], wx1, bias1) + hsum2(dB0);
        } else {
            preA0 = bias0 + xA0[0] + hsum2(aA0);
            preA1 = bias1 + xA1[0] + hsum2(dA0);
            preB0 = bias0 + xB0[0] + hsum2(aB0);
            preB1 = bias1 + xB1[0] + hsum2(dB0);
        }

        // activations: row g0 sigmoid (i or f); row g1 tanh if low (g) else sigmoid (o)
        float actA0 = sig_ap(preA0);
        float actB0 = sig_ap(preB0);
        float actA1 = low ? tanh_ap(preA1) : sig_ap(preA1);
        float actB1 = low ? tanh_ap(preB1) : sig_ap(preB1);

        // stage the pair the OTHER side needs
        if (low) igB_sh[unit] = make_float2(actB0, actB1);   // (i,g) of B
        else     foA_sh[unit] = make_float2(actA0, actA1);   // (f,o) of A

        // rotate prefetch window
        {
            int tn = (t + 4 < TT) ? (t + 4) : (TT - 1);
            if (LAYER == 0) {
                vA[0] = vA[1]; vA[1] = vA[2]; vA[2] = vA[3];
                vB[0] = vB[1]; vB[1] = vB[2]; vB[2] = vB[3];
                vA[3] = __ldg(x + xbA + tn);
                vB[3] = __ldg(x + xbB + tn);
            } else {
                xA0[0] = xA0[1]; xA0[1] = xA0[2]; xA0[2] = xA0[3];
                xA1[0] = xA1[1]; xA1[1] = xA1[2]; xA1[2] = xA1[3];
                xB0[0] = xB0[1]; xB0[1] = xB0[2]; xB0[2] = xB0[3];
                xB1[0] = xB1[1]; xB1[1] = xB1[2]; xB1[2] = xB1[3];
                xA0[3] = __half2float(__ldg(g_xp1 + pA + (size_t)tn * GG + g0));
                xA1[3] = __half2float(__ldg(g_xp1 + pA + (size_t)tn * GG + g1));
                xB0[3] = __half2float(__ldg(g_xp1 + pB + (size_t)tn * GG + g0));
                xB1[3] = __half2float(__ldg(g_xp1 + pB + (size_t)tn * GG + g1));
            }
        }

        __syncthreads();   // staged acts visible; h reads of this step done

        // ---- phase 2: every thread updates exactly one unit ----
        if (low) {
            // batch A unit 'unit': i,g local (actA0, actA1); f,o staged
            float2 fo = foA_sh[unit];
            c = fmaf(fo.x, c, actA0 * actA1);
            float hv = fo.y * tanh_ap(c);
            hA_sh[unit] = hv;
            if (LAYER == 0) g_y0[yA + (size_t)t * HH + unit] = __float2half_rn(hv);
            else            g_y1[yA + (size_t)t * HH + unit] = hv;
        } else {
            // batch B unit 'unit': f,o local (actB0, actB1); i,g staged
            float2 ig = igB_sh[unit];
            c = fmaf(actB0, c, ig.x * ig.y);
            float hv = actB1 * tanh_ap(c);
            hB_sh[unit] = hv;
            if (LAYER == 0) g_y0[yB + (size_t)t * HH + unit] = __float2half_rn(hv);
            else            g_y1[yB + (size_t)t * HH + unit] = hv;
        }
        __syncthreads();   // h ready for next step
    }
}

// ---------------- K2: xp1 = y0 @ Wih1^T -> fp16 ----------------
#define K2_ROWS 64
__global__ __launch_bounds__(256, 2) void xp_gemm_kernel(const float* __restrict__ Wih1)
{
    __shared__ __align__(16) float ys[K2_ROWS * HH];
    const int g = threadIdx.x;

    u64 w[32];
    {
        const ulonglong2* wr = (const ulonglong2*)(Wih1 + (size_t)g * HH);
#pragma unroll
        for (int i = 0; i < 16; i++) {
            ulonglong2 v = wr[i];
            w[2 * i]     = v.x;
            w[2 * i + 1] = v.y;
        }
    }

    const size_t r0 = (size_t)blockIdx.x * K2_ROWS;
    // cooperative load of 64 rows x 64 halves, convert to float in smem
    {
        const __half2* src = (const __half2*)(g_y0 + r0 * HH);
        float2* dst = (float2*)ys;
#pragma unroll
        for (int i = 0; i < 8; i++) {
            __half2 v = src[g + i * 256];
            dst[g + i * 256] = __half22float2(v);
        }
    }
    __syncthreads();

#pragma unroll 1
    for (int r = 0; r < K2_ROWS; r++) {
        const ulonglong2* hs = (const ulonglong2*)(ys + r * HH);
        u64 a0 = 0ull, a1 = 0ull, a2 = 0ull, a3 = 0ull;
#pragma unroll
        for (int i = 0; i < 8; i++) {
            ulonglong2 h1 = hs[2 * i];
            ulonglong2 h2 = hs[2 * i + 1];
            a0 = fma2(w[4 * i + 0], h1.x, a0);
            a1 = fma2(w[4 * i + 1], h1.y, a1);
            a2 = fma2(w[4 * i + 2], h2.x, a2);
            a3 = fma2(w[4 * i + 3], h2.y, a3);
        }
        a0 = add2(a0, a1);
        a2 = add2(a2, a3);
        a0 = add2(a0, a2);
        g_xp1[(r0 + r) * GG + g] = __float2half_rn(hsum2(a0));
    }
}

// ---------------- K4: pred = y1 @ Wlin^T + blin ----------------
__global__ __launch_bounds__(256) void out_kernel(
    const float* __restrict__ Wlin,
    const float* __restrict__ blin,
    float* __restrict__ out)
{
    __shared__ __align__(16) float wl[HH];
    const int tid = threadIdx.x;
    if (tid < HH) wl[tid] = Wlin[tid];
    __syncthreads();

    const size_t idx = (size_t)blockIdx.x * 256 + tid;
    const ulonglong2* row = (const ulonglong2*)(g_y1 + idx * HH);
    const ulonglong2* wv  = (const ulonglong2*)wl;
    u64 a0 = 0ull, a1 = 0ull, a2 = 0ull, a3 = 0ull;
#pragma unroll
    for (int i = 0; i < 8; i++) {
        ulonglong2 h1 = row[2 * i];
        ulonglong2 w1 = wv[2 * i];
        ulonglong2 h2 = row[2 * i + 1];
        ulonglong2 w2 = wv[2 * i + 1];
        a0 = fma2(w1.x, h1.x, a0);
        a1 = fma2(w1.y, h1.y, a1);
        a2 = fma2(w2.x, h2.x, a2);
        a3 = fma2(w2.y, h2.y, a3);
    }
    a0 = add2(a0, a1);
    a2 = add2(a2, a3);
    a0 = add2(a0, a2);
    out[idx] = hsum2(a0) + __ldg(blin);
}

// ---------------- launch ----------------
extern "C" void kernel_launch(void* const* d_in, const int* in_sizes, int n_in,
                              void* d_out, int out_size)
{
    const float* input = (const float*)d_in[0];   // [B,T]
    const float* h0    = (const float*)d_in[1];   // [2,B,H]
    const float* c0    = (const float*)d_in[2];   // [2,B,H]
    const float* Wih0  = (const float*)d_in[3];   // [256,1]
    const float* Whh0  = (const float*)d_in[4];   // [256,64]
    const float* bih0  = (const float*)d_in[5];
    const float* bhh0  = (const float*)d_in[6];
    const float* Wih1  = (const float*)d_in[7];   // [256,64]
    const float* Whh1  = (const float*)d_in[8];   // [256,64]
    const float* bih1  = (const float*)d_in[9];
    const float* bhh1  = (const float*)d_in[10];
    const float* Wlin  = (const float*)d_in[11];  // [1,64]
    const float* blin  = (const float*)d_in[12];  // [1]
    float* out = (float*)d_out;                   // [B,T]

    (void)in_sizes; (void)n_in; (void)out_size;

    // Layer 0 recurrence (2 batch rows per CTA) -> g_y0 (fp16)
    lstm_recur_kernel<0><<<BB / 2, 128>>>(input, Wih0, Whh0, bih0, bhh0, h0, c0);
    // xp1 = y0 @ Wih1^T -> g_xp1 (fp16)
    xp_gemm_kernel<<<(BB * TT) / K2_ROWS, 256>>>(Wih1);
    // Layer 1 recurrence -> g_y1
    lstm_recur_kernel<1><<<BB / 2, 128>>>(input /*unused*/, Wih0 /*unused*/, Whh1,
                                          bih1, bhh1,
                                          h0 + (size_t)BB * HH, c0 + (size_t)BB * HH);
    // pred = y1 @ Wlin^T + blin
    out_kernel<<<(BB * TT) / 256, 256>>>(Wlin, blin, out);
}

// round 7
// speedup vs baseline: 1.2092x; 1.2092x over previous
#include <cuda_runtime.h>
#include <cstddef>

#define BB 256      // batch
#define TT 2048     // time steps
#define HH 64       // hidden
#define GG 256      // 4*H gates

typedef unsigned long long u64;

// ---------------- packed f32x2 helpers (sm_100+) ----------------
__device__ __forceinline__ u64 fma2(u64 a, u64 b, u64 c) {
    u64 d;
    asm("fma.rn.f32x2 %0, %1, %2, %3;" : "=l"(d) : "l"(a), "l"(b), "l"(c));
    return d;
}
__device__ __forceinline__ u64 add2(u64 a, u64 b) {
    u64 d;
    asm("add.rn.f32x2 %0, %1, %2;" : "=l"(d) : "l"(a), "l"(b));
    return d;
}
__device__ __forceinline__ float hsum2(u64 a) {
    float lo = __uint_as_float((unsigned)(a & 0xffffffffull));
    float hi = __uint_as_float((unsigned)(a >> 32));
    return lo + hi;
}

// MUFU-based fast activations
__device__ __forceinline__ float tanh_ap(float x) {
    float y;
    asm("tanh.approx.f32 %0, %1;" : "=f"(y) : "f"(x));
    return y;
}
__device__ __forceinline__ float sig_ap(float x) {
    return fmaf(0.5f, tanh_ap(0.5f * x), 0.5f);
}

// ---------------- device scratch (no cudaMalloc allowed) ----------------
__device__ float g_y1[(size_t)BB * TT * HH];   // 128 MB, layer1 hidden outputs

// ---------------- Fused 2-layer LSTM kernel ----------------
// Grid = 128 CTAs (one per SM, single wave), 256 threads. CTA owns batch rows
// bA=2*bid, bB=2*bid+1. Thread g owns gate row g of Whh0, Whh1, Wih1 (regs).
// Per step:
//  seg1: FULL dots Whh0·h0 (A,B) and Whh1·h1prev (A,B); L0 acts -> gate smem
//  bar1
//  seg2: threads<128 update layer0 cell; y0 -> h0 smem
//  bar2
//  seg3: dots Wih1·y0 (A,B); add carried Whh1 partial + bias; L1 acts -> smem
//  bar3
//  seg4: threads<128 update layer1 cell; h1 -> smem + g_y1 gmem
//  bar4
// Gate smem interleaved [unit][i,f,g,o] so phase-2 reads one LDS.128.
__global__ __launch_bounds__(256, 1) void lstm_fused_kernel(
    const float* __restrict__ x,      // [B,T]
    const float* __restrict__ Wih0,   // [256,1]
    const float* __restrict__ Whh0,   // [256,64]
    const float* __restrict__ bih0,
    const float* __restrict__ bhh0,
    const float* __restrict__ Wih1,   // [256,64]
    const float* __restrict__ Whh1,   // [256,64]
    const float* __restrict__ bih1,
    const float* __restrict__ bhh1,
    const float* __restrict__ h0in,   // [2,B,64]
    const float* __restrict__ c0in)   // [2,B,64]
{
    __shared__ __align__(16) float hA0[HH], hB0[HH];   // layer0 hidden (y0)
    __shared__ __align__(16) float hA1[HH], hB1[HH];   // layer1 hidden
    __shared__ __align__(16) float gshA[GG], gshB[GG]; // gate staging [u*4+k]

    const int tid  = threadIdx.x;
    const int bA   = 2 * blockIdx.x;
    const int bB   = bA + 1;
    const int kind = tid >> 6;                 // 0:i 1:f 2:g 3:o
    const int gslot = ((tid & 63) << 2) | kind;
    const bool is_tanh_row = (kind == 2);

    // ---- weights in registers (full 64-element rows = 32 u64 each) ----
    u64 w0[32], w1[32], wi[32];
    {
        const ulonglong2* r0 = (const ulonglong2*)(Whh0 + (size_t)tid * HH);
        const ulonglong2* r1 = (const ulonglong2*)(Whh1 + (size_t)tid * HH);
        const ulonglong2* ri = (const ulonglong2*)(Wih1 + (size_t)tid * HH);
#pragma unroll
        for (int i = 0; i < 16; i++) {
            ulonglong2 v0 = r0[i];
            ulonglong2 v1 = r1[i];
            ulonglong2 vi = ri[i];
            w0[2 * i] = v0.x; w0[2 * i + 1] = v0.y;
            w1[2 * i] = v1.x; w1[2 * i + 1] = v1.y;
            wi[2 * i] = vi.x; wi[2 * i + 1] = vi.y;
        }
    }
    const float bias0 = bih0[tid] + bhh0[tid];
    const float bias1 = bih1[tid] + bhh1[tid];
    const float wx    = Wih0[tid];

    // cell states: threads<128 carry one unit of (cell0, cell1)
    const int side = (tid >> 6) & 1;      // tid<128: 0 = batch A, 1 = batch B
    const int u    = tid & 63;
    float cell0 = 0.0f, cell1 = 0.0f;
    if (tid < 128) {
        const int b = side ? bB : bA;
        cell0 = c0in[(size_t)b * HH + u];
        cell1 = c0in[(size_t)(BB + b) * HH + u];
        float h0v = h0in[(size_t)b * HH + u];
        float h1v = h0in[(size_t)(BB + b) * HH + u];
        if (side) { hB0[u] = h0v; hB1[u] = h1v; }
        else      { hA0[u] = h0v; hA1[u] = h1v; }
    }
    __syncthreads();

    const size_t xbA = (size_t)bA * TT;
    const size_t xbB = (size_t)bB * TT;
    const size_t yA  = (size_t)bA * TT * HH;
    const size_t yB  = (size_t)bB * TT * HH;

    // input prefetch, 2 deep (broadcast loads, L1-resident after first pass)
    float vA0 = __ldg(x + xbA), vA1 = __ldg(x + xbA + 1);
    float vB0 = __ldg(x + xbB), vB1 = __ldg(x + xbB + 1);

#pragma unroll 2
    for (int t = 0; t < TT; t++) {
        // ---- seg1: FULL dots Whh0·h0 (A,B) and Whh1·h1prev (A,B) ----
        u64 pA0a = 0ull, pA0b = 0ull, pB0a = 0ull, pB0b = 0ull;
        u64 pA1a = 0ull, pA1b = 0ull, pB1a = 0ull, pB1b = 0ull;
        {
            const ulonglong2* HA0 = (const ulonglong2*)hA0;
            const ulonglong2* HB0 = (const ulonglong2*)hB0;
            const ulonglong2* HA1 = (const ulonglong2*)hA1;
            const ulonglong2* HB1 = (const ulonglong2*)hB1;
#pragma unroll
            for (int i = 0; i < 8; i++) {
                ulonglong2 a0 = HA0[2 * i];
                ulonglong2 a0q = HA0[2 * i + 1];
                ulonglong2 b0 = HB0[2 * i];
                ulonglong2 b0q = HB0[2 * i + 1];
                ulonglong2 a1 = HA1[2 * i];
                ulonglong2 a1q = HA1[2 * i + 1];
                ulonglong2 b1 = HB1[2 * i];
                ulonglong2 b1q = HB1[2 * i + 1];
                pA0a = fma2(w0[4 * i + 0], a0.x,  pA0a);
                pA0b = fma2(w0[4 * i + 1], a0.y,  pA0b);
                pB0a = fma2(w0[4 * i + 0], b0.x,  pB0a);
                pB0b = fma2(w0[4 * i + 1], b0.y,  pB0b);
                pA1a = fma2(w1[4 * i + 0], a1.x,  pA1a);
                pA1b = fma2(w1[4 * i + 1], a1.y,  pA1b);
                pB1a = fma2(w1[4 * i + 0], b1.x,  pB1a);
                pB1b = fma2(w1[4 * i + 1], b1.y,  pB1b);
                pA0a = fma2(w0[4 * i + 2], a0q.x, pA0a);
                pA0b = fma2(w0[4 * i + 3], a0q.y, pA0b);
                pB0a = fma2(w0[4 * i + 2], b0q.x, pB0a);
                pB0b = fma2(w0[4 * i + 3], b0q.y, pB0b);
                pA1a = fma2(w1[4 * i + 2], a1q.x, pA1a);
                pA1b = fma2(w1[4 * i + 3], a1q.y, pA1b);
                pB1a = fma2(w1[4 * i + 2], b1q.x, pB1a);
                pB1b = fma2(w1[4 * i + 3], b1q.y, pB1b);
            }
        }
        float preA0 = fmaf(vA0, wx, bias0) + hsum2(add2(pA0a, pA0b));
        float preB0 = fmaf(vB0, wx, bias0) + hsum2(add2(pB0a, pB0b));
        float partA1 = hsum2(add2(pA1a, pA1b));   // Whh1·h1prev, batch A
        float partB1 = hsum2(add2(pB1a, pB1b));

        float actA0 = is_tanh_row ? tanh_ap(preA0) : sig_ap(preA0);
        float actB0 = is_tanh_row ? tanh_ap(preB0) : sig_ap(preB0);
        gshA[gslot] = actA0;
        gshB[gslot] = actB0;

        // rotate x prefetch
        vA0 = vA1; vB0 = vB1;
        {
            int tn = (t + 2 < TT) ? (t + 2) : (TT - 1);
            vA1 = __ldg(x + xbA + tn);
            vB1 = __ldg(x + xbB + tn);
        }
        __syncthreads();   // bar1: L0 gates staged

        // ---- seg2: layer0 cell update (threads < 128) ----
        if (tid < 128) {
            float4 G = ((const float4*)(side ? gshB : gshA))[u];
            cell0 = fmaf(G.y, cell0, G.x * G.z);
            float y0v = G.w * tanh_ap(cell0);
            (side ? hB0 : hA0)[u] = y0v;
        }
        __syncthreads();   // bar2: y0 published

        // ---- seg3: FULL dots Wih1·y0 (A,B), combine, L1 activations ----
        u64 qAa = 0ull, qAb = 0ull, qBa = 0ull, qBb = 0ull;
        {
            const ulonglong2* YA = (const ulonglong2*)hA0;
            const ulonglong2* YB = (const ulonglong2*)hB0;
#pragma unroll
            for (int i = 0; i < 8; i++) {
                ulonglong2 ya  = YA[2 * i];
                ulonglong2 yaq = YA[2 * i + 1];
                ulonglong2 yb  = YB[2 * i];
                ulonglong2 ybq = YB[2 * i + 1];
                qAa = fma2(wi[4 * i + 0], ya.x,  qAa);
                qAb = fma2(wi[4 * i + 1], ya.y,  qAb);
                qBa = fma2(wi[4 * i + 0], yb.x,  qBa);
                qBb = fma2(wi[4 * i + 1], yb.y,  qBb);
                qAa = fma2(wi[4 * i + 2], yaq.x, qAa);
                qAb = fma2(wi[4 * i + 3], yaq.y, qAb);
                qBa = fma2(wi[4 * i + 2], ybq.x, qBa);
                qBb = fma2(wi[4 * i + 3], ybq.y, qBb);
            }
        }
        float preA1 = bias1 + partA1 + hsum2(add2(qAa, qAb));
        float preB1 = bias1 + partB1 + hsum2(add2(qBa, qBb));
        float actA1 = is_tanh_row ? tanh_ap(preA1) : sig_ap(preA1);
        float actB1 = is_tanh_row ? tanh_ap(preB1) : sig_ap(preB1);
        gshA[gslot] = actA1;
        gshB[gslot] = actB1;
        __syncthreads();   // bar3: L1 gates staged

        // ---- seg4: layer1 cell update (threads < 128) ----
        if (tid < 128) {
            float4 G = ((const float4*)(side ? gshB : gshA))[u];
            cell1 = fmaf(G.y, cell1, G.x * G.z);
            float h1v = G.w * tanh_ap(cell1);
            (side ? hB1 : hA1)[u] = h1v;
            g_y1[(side ? yB : yA) + (size_t)t * HH + u] = h1v;
        }
        __syncthreads();   // bar4: h1 ready for next step's seg1
    }
}

// ---------------- out: pred = y1 @ Wlin^T + blin ----------------
__global__ __launch_bounds__(256) void out_kernel(
    const float* __restrict__ Wlin,
    const float* __restrict__ blin,
    float* __restrict__ out)
{
    __shared__ __align__(16) float wl[HH];
    const int tid = threadIdx.x;
    if (tid < HH) wl[tid] = Wlin[tid];
    __syncthreads();

    const size_t idx = (size_t)blockIdx.x * 256 + tid;
    const ulonglong2* row = (const ulonglong2*)(g_y1 + idx * HH);
    const ulonglong2* wv  = (const ulonglong2*)wl;
    u64 a0 = 0ull, a1 = 0ull, a2 = 0ull, a3 = 0ull;
#pragma unroll
    for (int i = 0; i < 8; i++) {
        ulonglong2 h1 = row[2 * i];
        ulonglong2 w1 = wv[2 * i];
        ulonglong2 h2 = row[2 * i + 1];
        ulonglong2 w2 = wv[2 * i + 1];
        a0 = fma2(w1.x, h1.x, a0);
        a1 = fma2(w1.y, h1.y, a1);
        a2 = fma2(w2.x, h2.x, a2);
        a3 = fma2(w2.y, h2.y, a3);
    }
    a0 = add2(a0, a1);
    a2 = add2(a2, a3);
    a0 = add2(a0, a2);
    out[idx] = hsum2(a0) + __ldg(blin);
}

// ---------------- launch ----------------
extern "C" void kernel_launch(void* const* d_in, const int* in_sizes, int n_in,
                              void* d_out, int out_size)
{
    const float* input = (const float*)d_in[0];   // [B,T]
    const float* h0    = (const float*)d_in[1];   // [2,B,H]
    const float* c0    = (const float*)d_in[2];   // [2,B,H]
    const float* Wih0  = (const float*)d_in[3];   // [256,1]
    const float* Whh0  = (const float*)d_in[4];   // [256,64]
    const float* bih0  = (const float*)d_in[5];
    const float* bhh0  = (const float*)d_in[6];
    const float* Wih1  = (const float*)d_in[7];   // [256,64]
    const float* Whh1  = (const float*)d_in[8];   // [256,64]
    const float* bih1  = (const float*)d_in[9];
    const float* bhh1  = (const float*)d_in[10];
    const float* Wlin  = (const float*)d_in[11];  // [1,64]
    const float* blin  = (const float*)d_in[12];  // [1]
    float* out = (float*)d_out;                   // [B,T]

    (void)in_sizes; (void)n_in; (void)out_size;

    // Fused 2-layer recurrence -> g_y1
    lstm_fused_kernel<<<BB / 2, 256>>>(input, Wih0, Whh0, bih0, bhh0,
                                       Wih1, Whh1, bih1, bhh1, h0, c0);
    // pred = y1 @ Wlin^T + blin
    out_kernel<<<(BB * TT) / 256, 256>>>(Wlin, blin, out);
}

// round 9
// speedup vs baseline: 1.4702x; 1.2159x over previous
#include <cuda_runtime.h>
#include <cuda_fp16.h>
#include <cstddef>

#define BB 256      // batch
#define TT 2048     // time steps
#define HH 64       // hidden
#define GG 256      // 4*H gates

typedef unsigned long long u64;

// ---------------- packed f32x2 helpers (sm_100+) ----------------
__device__ __forceinline__ u64 fma2(u64 a, u64 b, u64 c) {
    u64 d;
    asm("fma.rn.f32x2 %0, %1, %2, %3;" : "=l"(d) : "l"(a), "l"(b), "l"(c));
    return d;
}
__device__ __forceinline__ u64 add2(u64 a, u64 b) {
    u64 d;
    asm("add.rn.f32x2 %0, %1, %2;" : "=l"(d) : "l"(a), "l"(b));
    return d;
}
__device__ __forceinline__ float hsum2(u64 a) {
    float lo = __uint_as_float((unsigned)(a & 0xffffffffull));
    float hi = __uint_as_float((unsigned)(a >> 32));
    return lo + hi;
}

// MUFU-based fast activations
__device__ __forceinline__ float tanh_ap(float x) {
    float y;
    asm("tanh.approx.f32 %0, %1;" : "=f"(y) : "f"(x));
    return y;
}
__device__ __forceinline__ float sig_ap(float x) {
    return fmaf(0.5f, tanh_ap(0.5f * x), 0.5f);
}

// ---------------- device scratch (no cudaMalloc allowed) ----------------
__device__ __half g_y0h[(size_t)BB * TT * HH];   // 64 MB, layer0 outputs (fp16)
__device__ float  g_y1[(size_t)BB * TT * HH];    // 128 MB, layer1 outputs

// ---------------- Layer 0 recurrence (R4-proven structure) ----------------
// One CTA per batch row, 128 threads. Thread t owns gate rows t and t+128.
// Rows [0:64)=i [64:128)=f [128:192)=g [192:256)=o.
__global__ __launch_bounds__(128, 2) void lstm_l0_kernel(
    const float* __restrict__ x,     // [B,T]
    const float* __restrict__ Wih,   // [256,1]
    const float* __restrict__ Whh,   // [256,64]
    const float* __restrict__ bih,
    const float* __restrict__ bhh,
    const float* __restrict__ h0,    // [B,64] layer0 slice
    const float* __restrict__ c0)    // [B,64]
{
    __shared__ __align__(16) float  h_sh[HH];
    __shared__ __align__(8)  float2 act_sh[HH];   // (f,o) per unit

    const int tid  = threadIdx.x;
    const int b    = blockIdx.x;
    const int g0   = tid;
    const int g1   = tid + 128;
    const int unit = tid & 63;
    const bool low = (tid < 64);

    u64 w0[32], w1[32];
    {
        const ulonglong2* r0 = (const ulonglong2*)(Whh + (size_t)g0 * HH);
        const ulonglong2* r1 = (const ulonglong2*)(Whh + (size_t)g1 * HH);
#pragma unroll
        for (int i = 0; i < 16; i++) {
            ulonglong2 v0 = r0[i];
            ulonglong2 v1 = r1[i];
            w0[2 * i] = v0.x; w0[2 * i + 1] = v0.y;
            w1[2 * i] = v1.x; w1[2 * i + 1] = v1.y;
        }
    }
    const float bias0 = bih[g0] + bhh[g0];
    const float bias1 = bih[g1] + bhh[g1];
    const float wx0 = Wih[g0];
    const float wx1 = Wih[g1];

    float c = 0.0f;
    if (low) {
        h_sh[unit] = h0[(size_t)b * HH + unit];
        c          = c0[(size_t)b * HH + unit];
    }
    __syncthreads();

    const size_t xb = (size_t)b * TT;
    const size_t yb = (size_t)b * TT * HH;

    float v[4];
#pragma unroll
    for (int k = 0; k < 4; k++) v[k] = __ldg(x + xb + k);

#pragma unroll 4
    for (int t = 0; t < TT; t++) {
        u64 a0 = 0ull, a1 = 0ull, d0 = 0ull, d1 = 0ull;
        const ulonglong2* hs = (const ulonglong2*)h_sh;
#pragma unroll
        for (int i = 0; i < 8; i++) {
            ulonglong2 h1 = hs[2 * i];
            ulonglong2 h2 = hs[2 * i + 1];
            a0 = fma2(w0[4 * i + 0], h1.x, a0);
            d0 = fma2(w1[4 * i + 0], h1.x, d0);
            a1 = fma2(w0[4 * i + 1], h1.y, a1);
            d1 = fma2(w1[4 * i + 1], h1.y, d1);
            a0 = fma2(w0[4 * i + 2], h2.x, a0);
            d0 = fma2(w1[4 * i + 2], h2.x, d0);
            a1 = fma2(w0[4 * i + 3], h2.y, a1);
            d1 = fma2(w1[4 * i + 3], h2.y, d1);
        }
        float pre0 = fmaf(v[0], wx0, bias0) + hsum2(add2(a0, a1));
        float pre1 = fmaf(v[0], wx1, bias1) + hsum2(add2(d0, d1));

        float act0 = sig_ap(pre0);                              // i or f
        float act1 = low ? tanh_ap(pre1) : sig_ap(pre1);        // g or o
        if (!low) act_sh[unit] = make_float2(act0, act1);       // (f,o)

        v[0] = v[1]; v[1] = v[2]; v[2] = v[3];
        {
            int tn = (t + 4 < TT) ? (t + 4) : (TT - 1);
            v[3] = __ldg(x + xb + tn);
        }
        __syncthreads();   // gates staged; h reads done

        if (low) {
            float2 fo = act_sh[unit];
            c = fmaf(fo.x, c, act0 * act1);
            float hv = fo.y * tanh_ap(c);
            h_sh[unit] = hv;
            g_y0h[yb + (size_t)t * HH + unit] = __float2half_rn(hv);
        }
        __syncthreads();   // h ready
    }
}

// ---------------- Layer 1 recurrence with fused Wih1·y0 ----------------
// Same skeleton; xp computed in-kernel: y0[t] (64 fp16 = 128B) staged in a
// 4-slot smem ring by threads 0-7 (one uint4 each), prefetched 3 steps ahead.
// Wih1 rows live in half2 registers; dot via HFMA2 (4-way split accumulators),
// fully independent of the recurrent chain -> fills idle issue slots.
__global__ __launch_bounds__(128, 2) void lstm_l1_kernel(
    const float* __restrict__ Whh,   // Whh1 [256,64]
    const float* __restrict__ bih,
    const float* __restrict__ bhh,
    const float* __restrict__ Wih1,  // [256,64]
    const float* __restrict__ h0,    // [B,64] layer1 slice
    const float* __restrict__ c0)    // [B,64]
{
    __shared__ __align__(16) float  h_sh[HH];
    __shared__ __align__(8)  float2 act_sh[HH];
    __shared__ __align__(16) __half ybuf[4][HH];   // y0[t] ring

    const int tid  = threadIdx.x;
    const int b    = blockIdx.x;
    const int g0   = tid;
    const int g1   = tid + 128;
    const int unit = tid & 63;
    const bool low = (tid < 64);

    u64 w0[32], w1[32];
    {
        const ulonglong2* r0 = (const ulonglong2*)(Whh + (size_t)g0 * HH);
        const ulonglong2* r1 = (const ulonglong2*)(Whh + (size_t)g1 * HH);
#pragma unroll
        for (int i = 0; i < 16; i++) {
            ulonglong2 v0 = r0[i];
            ulonglong2 v1 = r1[i];
            w0[2 * i] = v0.x; w0[2 * i + 1] = v0.y;
            w1[2 * i] = v1.x; w1[2 * i + 1] = v1.y;
        }
    }
    // Wih1 rows g0, g1 as half2 (32 regs each)
    __half2 wia[32], wib[32];
    {
        const float2* ria = (const float2*)(Wih1 + (size_t)g0 * HH);
        const float2* rib = (const float2*)(Wih1 + (size_t)g1 * HH);
#pragma unroll
        for (int i = 0; i < 32; i++) {
            float2 fa = ria[i];
            float2 fb = rib[i];
            wia[i] = __floats2half2_rn(fa.x, fa.y);
            wib[i] = __floats2half2_rn(fb.x, fb.y);
        }
    }
    const float bias0 = bih[g0] + bhh[g0];
    const float bias1 = bih[g1] + bhh[g1];

    float c = 0.0f;
    if (low) {
        h_sh[unit] = h0[(size_t)b * HH + unit];
        c          = c0[(size_t)b * HH + unit];
    }

    const size_t yb = (size_t)b * TT * HH;
    const uint4* ysrc = (const uint4*)(g_y0h + yb);   // 8 uint4 per time row

    // initial ring fill: slots 0..2 = y0[0..2]
    if (tid < 8) {
#pragma unroll
        for (int k = 0; k < 3; k++)
            *(uint4*)&ybuf[k][tid * 8] = __ldg(ysrc + (size_t)k * 8 + tid);
    }
    __syncthreads();

#pragma unroll 4
    for (int t = 0; t < TT; t++) {
        const int slot = t & 3;

        // issue prefetch of y0[t+3] (landed into ring after bar1)
        uint4 pf;
        if (tid < 8) {
            int tn = (t + 3 < TT) ? (t + 3) : (TT - 1);
            pf = __ldg(ysrc + (size_t)tn * 8 + tid);
        }

        // recurrent dots (critical path)
        u64 a0 = 0ull, a1 = 0ull, d0 = 0ull, d1 = 0ull;
        const ulonglong2* hs = (const ulonglong2*)h_sh;
#pragma unroll
        for (int i = 0; i < 8; i++) {
            ulonglong2 h1 = hs[2 * i];
            ulonglong2 h2 = hs[2 * i + 1];
            a0 = fma2(w0[4 * i + 0], h1.x, a0);
            d0 = fma2(w1[4 * i + 0], h1.x, d0);
            a1 = fma2(w0[4 * i + 1], h1.y, a1);
            d1 = fma2(w1[4 * i + 1], h1.y, d1);
            a0 = fma2(w0[4 * i + 2], h2.x, a0);
            d0 = fma2(w1[4 * i + 2], h2.x, d0);
            a1 = fma2(w0[4 * i + 3], h2.y, a1);
            d1 = fma2(w1[4 * i + 3], h2.y, d1);
        }

        // xp = Wih1·y0[t] (independent of chain; half2, split accumulators)
        __half2 ha0 = __float2half2_rn(0.0f), ha1 = ha0;
        __half2 hb0 = ha0, hb1 = ha0;
        {
            const uint4* Y = (const uint4*)ybuf[slot];
#pragma unroll
            for (int i = 0; i < 8; i++) {
                uint4 y4 = Y[i];
                __half2 y0p = *reinterpret_cast<__half2*>(&y4.x);
                __half2 y1p = *reinterpret_cast<__half2*>(&y4.y);
                __half2 y2p = *reinterpret_cast<__half2*>(&y4.z);
                __half2 y3p = *reinterpret_cast<__half2*>(&y4.w);
                ha0 = __hfma2(wia[4 * i + 0], y0p, ha0);
                hb0 = __hfma2(wib[4 * i + 0], y0p, hb0);
                ha1 = __hfma2(wia[4 * i + 1], y1p, ha1);
                hb1 = __hfma2(wib[4 * i + 1], y1p, hb1);
                ha0 = __hfma2(wia[4 * i + 2], y2p, ha0);
                hb0 = __hfma2(wib[4 * i + 2], y2p, hb0);
                ha1 = __hfma2(wia[4 * i + 3], y3p, ha1);
                hb1 = __hfma2(wib[4 * i + 3], y3p, hb1);
            }
        }
        float2 fa0 = __half22float2(ha0);
        float2 fa1 = __half22float2(ha1);
        float2 fb0 = __half22float2(hb0);
        float2 fb1 = __half22float2(hb1);
        float xp0 = (fa0.x + fa0.y) + (fa1.x + fa1.y);
        float xp1 = (fb0.x + fb0.y) + (fb1.x + fb1.y);

        float pre0 = bias0 + xp0 + hsum2(add2(a0, a1));
        float pre1 = bias1 + xp1 + hsum2(add2(d0, d1));

        float act0 = sig_ap(pre0);
        float act1 = low ? tanh_ap(pre1) : sig_ap(pre1);
        if (!low) act_sh[unit] = make_float2(act0, act1);

        __syncthreads();   // bar1: gates staged; ybuf[slot] reads done

        // land prefetch into slot (t+3)&3 (its old contents consumed at t-1)
        if (tid < 8) *(uint4*)&ybuf[(t + 3) & 3][tid * 8] = pf;

        if (low) {
            float2 fo = act_sh[unit];
            c = fmaf(fo.x, c, act0 * act1);
            float hv = fo.y * tanh_ap(c);
            h_sh[unit] = hv;
            g_y1[yb + (size_t)t * HH + unit] = hv;
        }
        __syncthreads();   // bar2: h ready
    }
}

// ---------------- out: pred = y1 @ Wlin^T + blin ----------------
__global__ __launch_bounds__(256) void out_kernel(
    const float* __restrict__ Wlin,
    const float* __restrict__ blin,
    float* __restrict__ out)
{
    __shared__ __align__(16) float wl[HH];
    const int tid = threadIdx.x;
    if (tid < HH) wl[tid] = Wlin[tid];
    __syncthreads();

    const size_t idx = (size_t)blockIdx.x * 256 + tid;
    const ulonglong2* row = (const ulonglong2*)(g_y1 + idx * HH);
    const ulonglong2* wv  = (const ulonglong2*)wl;
    u64 a0 = 0ull, a1 = 0ull, a2 = 0ull, a3 = 0ull;
#pragma unroll
    for (int i = 0; i < 8; i++) {
        ulonglong2 h1 = row[2 * i];
        ulonglong2 w1 = wv[2 * i];
        ulonglong2 h2 = row[2 * i + 1];
        ulonglong2 w2 = wv[2 * i + 1];
        a0 = fma2(w1.x, h1.x, a0);
        a1 = fma2(w1.y, h1.y, a1);
        a2 = fma2(w2.x, h2.x, a2);
        a3 = fma2(w2.y, h2.y, a3);
    }
    a0 = add2(a0, a1);
    a2 = add2(a2, a3);
    a0 = add2(a0, a2);
    out[idx] = hsum2(a0) + __ldg(blin);
}

// ---------------- launch ----------------
extern "C" void kernel_launch(void* const* d_in, const int* in_sizes, int n_in,
                              void* d_out, int out_size)
{
    const float* input = (const float*)d_in[0];   // [B,T]
    const float* h0    = (const float*)d_in[1];   // [2,B,H]
    const float* c0    = (const float*)d_in[2];   // [2,B,H]
    const float* Wih0  = (const float*)d_in[3];   // [256,1]
    const float* Whh0  = (const float*)d_in[4];   // [256,64]
    const float* bih0  = (const float*)d_in[5];
    const float* bhh0  = (const float*)d_in[6];
    const float* Wih1  = (const float*)d_in[7];   // [256,64]
    const float* Whh1  = (const float*)d_in[8];   // [256,64]
    const float* bih1  = (const float*)d_in[9];
    const float* bhh1  = (const float*)d_in[10];
    const float* Wlin  = (const float*)d_in[11];  // [1,64]
    const float* blin  = (const float*)d_in[12];  // [1]
    float* out = (float*)d_out;                   // [B,T]

    (void)in_sizes; (void)n_in; (void)out_size;

    // Layer 0 -> g_y0h (fp16)
    lstm_l0_kernel<<<BB, 128>>>(input, Wih0, Whh0, bih0, bhh0, h0, c0);
    // Layer 1 (fused Wih1·y0) -> g_y1
    lstm_l1_kernel<<<BB, 128>>>(Whh1, bih1, bhh1, Wih1,
                                h0 + (size_t)BB * HH, c0 + (size_t)BB * HH);
    // pred = y1 @ Wlin^T + blin
    out_kernel<<<(BB * TT) / 256, 256>>>(Wlin, blin, out);
}